// round 1
// baseline (speedup 1.0000x reference)
#include <cuda_runtime.h>

#define NPIX 6400
#define IMGW 80
#define CIN 256
#define CK 128
#define CV 256

// ---------------- scratch (device globals; no allocation allowed) ----------------
__device__ float g_K[2 * NPIX * CK];                 // [b][n][c]   6.55 MB
__device__ float g_V[(size_t)2 * NPIX * CV];         // [b][n][c]  13.1 MB
__device__ float g_S[(size_t)2 * NPIX * NPIX];       // [b][n][m] 327.7 MB
__device__ float g_ctx[(size_t)2 * NPIX * CV];       // [b][n][c]  13.1 MB
__device__ float g_rs[2 * NPIX];                     // 1/rowsum
__device__ float g_wkT[CIN * CK];                    // folded+transposed K weights [i][c]
__device__ float g_kbias[CK];
__device__ float g_wvT[9 * CIN * CV];                // transposed V weights [t][i][c]

// ---------------- weight prep: fold BN into 1x1 conv, transpose weights ----------
__global__ void prep_kernel(const float* __restrict__ wk, const float* __restrict__ bk,
                            const float* __restrict__ gamma, const float* __restrict__ beta,
                            const float* __restrict__ rmean, const float* __restrict__ rvar,
                            const float* __restrict__ wv) {
    int tid = blockIdx.x * blockDim.x + threadIdx.x;
    int nth = gridDim.x * blockDim.x;
    if (tid < CK) {
        float inv = gamma[tid] * rsqrtf(rvar[tid] + 1e-5f);
        g_kbias[tid] = bk[tid] * inv + beta[tid] - rmean[tid] * inv;
    }
    for (int idx = tid; idx < CK * CIN; idx += nth) {
        int c = idx / CIN, i = idx - c * CIN;
        float inv = gamma[c] * rsqrtf(rvar[c] + 1e-5f);
        g_wkT[i * CK + c] = wk[idx] * inv;
    }
    for (int idx = tid; idx < 9 * CIN * CV; idx += nth) {
        int c = idx / (CIN * 9);
        int rem = idx - c * CIN * 9;
        int i = rem / 9;
        int t = rem - i * 9;
        g_wvT[(t * CIN + i) * CV + c] = wv[idx];
    }
}

// ---------------- conv as implicit GEMM ------------------------------------------
// out[b][n][c] = bias[c] + sum_t sum_i wT[t][i][c] * x[b][i][n + off_t]
// BM = 128 pixels, BN = 64 channels, BK = 16, micro 8x4, 256 threads.
template <int COUT, int NTAPS>
__global__ void conv_kernel(const float* __restrict__ x, const float* __restrict__ bias_in) {
    __shared__ float As[16][132];
    __shared__ float Bs[16][68];
    const float* wT   = (NTAPS == 9) ? g_wvT : g_wkT;
    const float* bias = (NTAPS == 9) ? bias_in : g_kbias;
    float* outp       = (NTAPS == 9) ? g_V : g_K;

    int b  = blockIdx.z;
    int n0 = blockIdx.x * 128;
    int c0 = blockIdx.y * 64;
    const float* xb = x + (size_t)b * CIN * NPIX;

    int tid  = threadIdx.x;
    int m    = tid & 127;       // pixel within tile (A load)
    int kb   = tid >> 7;        // 0..1
    int cb   = tid & 63;        // channel within tile (B load)
    int kbb  = tid >> 6;        // 0..3
    int ng   = n0 + m;
    int ypix = ng / IMGW;
    int xpix = ng - ypix * IMGW;
    int tx = tid & 15, ty = tid >> 4;

    float acc[8][4];
#pragma unroll
    for (int r = 0; r < 8; r++)
#pragma unroll
        for (int c = 0; c < 4; c++) acc[r][c] = 0.f;

    for (int t = 0; t < NTAPS; t++) {
        int dy = (NTAPS == 9) ? (t / 3 - 1) : 0;
        int dx = (NTAPS == 9) ? (t % 3 - 1) : 0;
        bool valid = ((unsigned)(ypix + dy) < (unsigned)IMGW) &&
                     ((unsigned)(xpix + dx) < (unsigned)IMGW);
        int off = dy * IMGW + dx;
        for (int i0 = 0; i0 < CIN; i0 += 16) {
            __syncthreads();
#pragma unroll
            for (int l = 0; l < 8; l++) {
                int kk = kb + 2 * l;
                As[kk][m] = valid ? xb[(size_t)(i0 + kk) * NPIX + ng + off] : 0.f;
            }
#pragma unroll
            for (int l = 0; l < 4; l++) {
                int kk = kbb + 4 * l;
                Bs[kk][cb] = wT[(size_t)(t * CIN + i0 + kk) * COUT + c0 + cb];
            }
            __syncthreads();
#pragma unroll
            for (int kk = 0; kk < 16; kk++) {
                float a[8], bv[4];
#pragma unroll
                for (int r = 0; r < 8; r++) a[r] = As[kk][ty * 8 + r];
#pragma unroll
                for (int c = 0; c < 4; c++) bv[c] = Bs[kk][tx * 4 + c];
#pragma unroll
                for (int r = 0; r < 8; r++)
#pragma unroll
                    for (int c = 0; c < 4; c++) acc[r][c] += a[r] * bv[c];
            }
        }
    }
#pragma unroll
    for (int r = 0; r < 8; r++) {
        int row = n0 + ty * 8 + r;
        float4 v;
        v.x = acc[r][0] + bias[c0 + tx * 4 + 0];
        v.y = acc[r][1] + bias[c0 + tx * 4 + 1];
        v.z = acc[r][2] + bias[c0 + tx * 4 + 2];
        v.w = acc[r][3] + bias[c0 + tx * 4 + 3];
        *(float4*)(outp + (size_t)(b * NPIX + row) * COUT + c0 + tx * 4) = v;
    }
}

// ---------------- S = K @ K^T  (M=N=6400, K=128) ----------------------------------
__global__ void gemm_s_kernel() {
    __shared__ float As[16][132];
    __shared__ float Bs[16][132];
    int b  = blockIdx.z;
    int m0 = blockIdx.y * 128;
    int n0 = blockIdx.x * 128;
    const float* Kb = g_K + (size_t)b * NPIX * CK;
    int tid  = threadIdx.x;
    int f4   = tid & 3;
    int lrow = tid >> 2;
    int tx = tid & 15, ty = tid >> 4;

    float acc[8][8];
#pragma unroll
    for (int r = 0; r < 8; r++)
#pragma unroll
        for (int c = 0; c < 8; c++) acc[r][c] = 0.f;

    for (int k0 = 0; k0 < CK; k0 += 16) {
        __syncthreads();
#pragma unroll
        for (int l = 0; l < 2; l++) {
            int row = lrow + 64 * l;
            float4 va = *(const float4*)(Kb + (size_t)(m0 + row) * CK + k0 + f4 * 4);
            As[f4 * 4 + 0][row] = va.x; As[f4 * 4 + 1][row] = va.y;
            As[f4 * 4 + 2][row] = va.z; As[f4 * 4 + 3][row] = va.w;
            float4 vb = *(const float4*)(Kb + (size_t)(n0 + row) * CK + k0 + f4 * 4);
            Bs[f4 * 4 + 0][row] = vb.x; Bs[f4 * 4 + 1][row] = vb.y;
            Bs[f4 * 4 + 2][row] = vb.z; Bs[f4 * 4 + 3][row] = vb.w;
        }
        __syncthreads();
#pragma unroll
        for (int kk = 0; kk < 16; kk++) {
            float a[8], bv[8];
#pragma unroll
            for (int r = 0; r < 8; r++) a[r] = As[kk][ty * 8 + r];
#pragma unroll
            for (int c = 0; c < 8; c++) bv[c] = Bs[kk][tx * 8 + c];
#pragma unroll
            for (int r = 0; r < 8; r++)
#pragma unroll
                for (int c = 0; c < 8; c++) acc[r][c] += a[r] * bv[c];
        }
    }
    float* Sb = g_S + (size_t)b * NPIX * NPIX;
#pragma unroll
    for (int r = 0; r < 8; r++) {
        size_t base = (size_t)(m0 + ty * 8 + r) * NPIX + n0 + tx * 8;
        float4 v0 = make_float4(acc[r][0], acc[r][1], acc[r][2], acc[r][3]);
        float4 v1 = make_float4(acc[r][4], acc[r][5], acc[r][6], acc[r][7]);
        *(float4*)(Sb + base)     = v0;
        *(float4*)(Sb + base + 4) = v1;
    }
}

// ---------------- row softmax (in-place exp; store 1/sum) -------------------------
__global__ void softmax_kernel() {
    int b   = blockIdx.y;
    int row = blockIdx.x;
    float* p = g_S + ((size_t)b * NPIX + row) * NPIX;
    int tid = threadIdx.x;
    __shared__ float red[256];

    float mx = -3.4e38f;
    for (int j = tid; j < NPIX; j += 256) mx = fmaxf(mx, p[j]);
    red[tid] = mx;
    __syncthreads();
    for (int s = 128; s > 0; s >>= 1) {
        if (tid < s) red[tid] = fmaxf(red[tid], red[tid + s]);
        __syncthreads();
    }
    float m = red[0];
    __syncthreads();

    float sum = 0.f;
    for (int j = tid; j < NPIX; j += 256) {
        float e = __expf(p[j] - m);
        p[j] = e;
        sum += e;
    }
    red[tid] = sum;
    __syncthreads();
    for (int s = 128; s > 0; s >>= 1) {
        if (tid < s) red[tid] += red[tid + s];
        __syncthreads();
    }
    if (tid == 0) g_rs[b * NPIX + row] = 1.0f / red[0];
}

// ---------------- ctx = rowscale * (P @ V)  (M=6400, N=256, K=6400) ---------------
// BM=128, BN=64, BK=16, micro 8x4.
__global__ void gemm_ctx_kernel() {
    __shared__ float As[16][132];
    __shared__ float Bs[16][68];
    int b  = blockIdx.z;
    int m0 = blockIdx.y * 128;
    int c0 = blockIdx.x * 64;
    const float* P = g_S + (size_t)b * NPIX * NPIX;
    const float* V = g_V + (size_t)b * NPIX * CV;

    int tid  = threadIdx.x;
    int f4   = tid & 3;
    int lrow = tid >> 2;
    int bf4  = tid & 15;
    int bkk  = tid >> 4;
    int tx = tid & 15, ty = tid >> 4;

    float acc[8][4];
#pragma unroll
    for (int r = 0; r < 8; r++)
#pragma unroll
        for (int c = 0; c < 4; c++) acc[r][c] = 0.f;

    for (int kt = 0; kt < NPIX; kt += 16) {
        __syncthreads();
#pragma unroll
        for (int l = 0; l < 2; l++) {
            int row = lrow + 64 * l;
            float4 va = *(const float4*)(P + (size_t)(m0 + row) * NPIX + kt + f4 * 4);
            As[f4 * 4 + 0][row] = va.x; As[f4 * 4 + 1][row] = va.y;
            As[f4 * 4 + 2][row] = va.z; As[f4 * 4 + 3][row] = va.w;
        }
        {
            float4 vb = *(const float4*)(V + (size_t)(kt + bkk) * CV + c0 + bf4 * 4);
            *(float4*)&Bs[bkk][bf4 * 4] = vb;
        }
        __syncthreads();
#pragma unroll
        for (int kk = 0; kk < 16; kk++) {
            float a[8], bv[4];
#pragma unroll
            for (int r = 0; r < 8; r++) a[r] = As[kk][ty * 8 + r];
#pragma unroll
            for (int c = 0; c < 4; c++) bv[c] = Bs[kk][tx * 4 + c];
#pragma unroll
            for (int r = 0; r < 8; r++)
#pragma unroll
                for (int c = 0; c < 4; c++) acc[r][c] += a[r] * bv[c];
        }
    }
#pragma unroll
    for (int r = 0; r < 8; r++) {
        int row  = m0 + ty * 8 + r;
        float sc = g_rs[b * NPIX + row];
        float4 v = make_float4(acc[r][0] * sc, acc[r][1] * sc, acc[r][2] * sc, acc[r][3] * sc);
        *(float4*)(g_ctx + (size_t)(b * NPIX + row) * CV + c0 + tx * 4) = v;
    }
}

// ---------------- out[b][co][n] = ww @ ctx^T + bw + x -----------------------------
// gemm_nt: A = ww [256, 256], B = ctx_b [6400, 256]. BM=BN=128, micro 8x8.
__global__ void gemm_out_kernel(const float* __restrict__ ww, const float* __restrict__ bw,
                                const float* __restrict__ x, float* __restrict__ out) {
    __shared__ float As[16][132];
    __shared__ float Bs[16][132];
    int b   = blockIdx.z;
    int co0 = blockIdx.y * 128;
    int n0  = blockIdx.x * 128;
    const float* ctxb = g_ctx + (size_t)b * NPIX * CV;

    int tid  = threadIdx.x;
    int f4   = tid & 3;
    int lrow = tid >> 2;
    int tx = tid & 15, ty = tid >> 4;

    float acc[8][8];
#pragma unroll
    for (int r = 0; r < 8; r++)
#pragma unroll
        for (int c = 0; c < 8; c++) acc[r][c] = 0.f;

    for (int k0 = 0; k0 < CV; k0 += 16) {
        __syncthreads();
#pragma unroll
        for (int l = 0; l < 2; l++) {
            int row = lrow + 64 * l;
            float4 va = *(const float4*)(ww + (size_t)(co0 + row) * CV + k0 + f4 * 4);
            As[f4 * 4 + 0][row] = va.x; As[f4 * 4 + 1][row] = va.y;
            As[f4 * 4 + 2][row] = va.z; As[f4 * 4 + 3][row] = va.w;
            float4 vb = *(const float4*)(ctxb + (size_t)(n0 + row) * CV + k0 + f4 * 4);
            Bs[f4 * 4 + 0][row] = vb.x; Bs[f4 * 4 + 1][row] = vb.y;
            Bs[f4 * 4 + 2][row] = vb.z; Bs[f4 * 4 + 3][row] = vb.w;
        }
        __syncthreads();
#pragma unroll
        for (int kk = 0; kk < 16; kk++) {
            float a[8], bv[8];
#pragma unroll
            for (int r = 0; r < 8; r++) a[r] = As[kk][ty * 8 + r];
#pragma unroll
            for (int c = 0; c < 8; c++) bv[c] = Bs[kk][tx * 8 + c];
#pragma unroll
            for (int r = 0; r < 8; r++)
#pragma unroll
                for (int c = 0; c < 8; c++) acc[r][c] += a[r] * bv[c];
        }
    }
#pragma unroll
    for (int r = 0; r < 8; r++) {
        int co = co0 + ty * 8 + r;
        float bwv = bw[co];
        size_t xbase = ((size_t)b * CIN + co) * NPIX + n0 + tx * 8;
        size_t obase = ((size_t)b * CV  + co) * NPIX + n0 + tx * 8;
        float4 x0 = *(const float4*)(x + xbase);
        float4 x1 = *(const float4*)(x + xbase + 4);
        float4 o0, o1;
        o0.x = acc[r][0] + bwv + x0.x; o0.y = acc[r][1] + bwv + x0.y;
        o0.z = acc[r][2] + bwv + x0.z; o0.w = acc[r][3] + bwv + x0.w;
        o1.x = acc[r][4] + bwv + x1.x; o1.y = acc[r][5] + bwv + x1.y;
        o1.z = acc[r][6] + bwv + x1.z; o1.w = acc[r][7] + bwv + x1.w;
        *(float4*)(out + obase)     = o0;
        *(float4*)(out + obase + 4) = o1;
    }
}

// ---------------- launch ----------------------------------------------------------
extern "C" void kernel_launch(void* const* d_in, const int* in_sizes, int n_in,
                              void* d_out, int out_size) {
    (void)in_sizes; (void)n_in; (void)out_size;
    const float* x     = (const float*)d_in[0];
    const float* wk    = (const float*)d_in[1];
    const float* bk    = (const float*)d_in[2];
    const float* gamma = (const float*)d_in[3];
    const float* beta  = (const float*)d_in[4];
    const float* rmean = (const float*)d_in[5];
    const float* rvar  = (const float*)d_in[6];
    const float* wv    = (const float*)d_in[7];
    const float* bv    = (const float*)d_in[8];
    const float* ww    = (const float*)d_in[9];
    const float* bw    = (const float*)d_in[10];
    float* out = (float*)d_out;

    prep_kernel<<<256, 256>>>(wk, bk, gamma, beta, rmean, rvar, wv);
    conv_kernel<CK, 1><<<dim3(NPIX / 128, CK / 64, 2), 256>>>(x, bv);
    conv_kernel<CV, 9><<<dim3(NPIX / 128, CV / 64, 2), 256>>>(x, bv);
    gemm_s_kernel<<<dim3(NPIX / 128, NPIX / 128, 2), 256>>>();
    softmax_kernel<<<dim3(NPIX, 2), 256>>>();
    gemm_ctx_kernel<<<dim3(CV / 64, NPIX / 128, 2), 256>>>();
    gemm_out_kernel<<<dim3(NPIX / 128, CV / 128, 2), 256>>>(ww, bw, x, out);
}

// round 3
// speedup vs baseline: 5.0334x; 5.0334x over previous
#include <cuda_runtime.h>
#include <cuda_bf16.h>
#include <stdint.h>

#define NPIX 6400
#define IMGW 80
#define CIN 256
#define CK 128
#define CV 256

// ---------------- scratch (device globals; no allocation allowed) ----------------
__device__ __nv_bfloat16 g_xT[(size_t)2 * NPIX * CIN];  // [b][n][c]  6.6 MB
__device__ __nv_bfloat16 g_Kb[(size_t)2 * NPIX * CK];   // [b][n][c]  3.3 MB
__device__ __nv_bfloat16 g_V[(size_t)2 * NPIX * CV];    // [b][n][c]  6.6 MB
__device__ __nv_bfloat16 g_Sb[(size_t)2 * NPIX * NPIX]; // [b][q][k]  164 MB
__device__ float g_ctx[(size_t)2 * NPIX * CV];          // [b][n][c]  13.1 MB
__device__ float g_kbias[CK];
__device__ __nv_bfloat16 g_wkb[CK * CIN];               // folded K weights [ck][cin]
__device__ __nv_bfloat16 g_wvb[9 * CV * CIN];           // V weights [tap][cv][cin]

// ---------------- PTX helpers (sm_80-class: ldmatrix / mma.sync / cp.async) ------
__device__ __forceinline__ uint32_t smem_u32(const void* p) {
    uint32_t a;
    asm("{ .reg .u64 t; cvta.to.shared.u64 t, %1; cvt.u32.u64 %0, t; }" : "=r"(a) : "l"(p));
    return a;
}
__device__ __forceinline__ void ldsm4(uint32_t* r, uint32_t addr) {
    asm volatile("ldmatrix.sync.aligned.m8n8.x4.shared.b16 {%0,%1,%2,%3}, [%4];"
                 : "=r"(r[0]), "=r"(r[1]), "=r"(r[2]), "=r"(r[3]) : "r"(addr));
}
__device__ __forceinline__ void ldsm4t(uint32_t* r, uint32_t addr) {
    asm volatile("ldmatrix.sync.aligned.m8n8.x4.trans.shared.b16 {%0,%1,%2,%3}, [%4];"
                 : "=r"(r[0]), "=r"(r[1]), "=r"(r[2]), "=r"(r[3]) : "r"(addr));
}
__device__ __forceinline__ void mma_bf16(float* c, const uint32_t* a, uint32_t b0, uint32_t b1) {
    asm volatile("mma.sync.aligned.m16n8k16.row.col.f32.bf16.bf16.f32 "
                 "{%0,%1,%2,%3}, {%4,%5,%6,%7}, {%8,%9}, {%0,%1,%2,%3};"
                 : "+f"(c[0]), "+f"(c[1]), "+f"(c[2]), "+f"(c[3])
                 : "r"(a[0]), "r"(a[1]), "r"(a[2]), "r"(a[3]), "r"(b0), "r"(b1));
}
__device__ __forceinline__ void cpa16(uint32_t dst, const void* src, int sz) {
    asm volatile("cp.async.cg.shared.global [%0], [%1], 16, %2;"
                 :: "r"(dst), "l"(src), "r"(sz));
}
#define CP_COMMIT() asm volatile("cp.async.commit_group;" ::: "memory")
#define CP_WAIT(n)  asm volatile("cp.async.wait_group %0;" :: "n"(n) : "memory")

// ---------------- weight prep ----------------
__global__ void prep_kernel(const float* __restrict__ wk, const float* __restrict__ bk,
                            const float* __restrict__ gamma, const float* __restrict__ beta,
                            const float* __restrict__ rmean, const float* __restrict__ rvar,
                            const float* __restrict__ wv) {
    int tid = blockIdx.x * blockDim.x + threadIdx.x;
    int nth = gridDim.x * blockDim.x;
    if (tid < CK) {
        float inv = gamma[tid] * rsqrtf(rvar[tid] + 1e-5f);
        g_kbias[tid] = bk[tid] * inv + beta[tid] - rmean[tid] * inv;
    }
    for (int idx = tid; idx < CK * CIN; idx += nth) {
        int c = idx / CIN;
        float inv = gamma[c] * rsqrtf(rvar[c] + 1e-5f);
        g_wkb[idx] = __float2bfloat16(wk[idx] * inv);
    }
    for (int idx = tid; idx < 9 * CV * CIN; idx += nth) {
        int t = idx / (CV * CIN);
        int rem = idx - t * CV * CIN;
        int o = rem / CIN;
        int i = rem - o * CIN;
        g_wvb[idx] = __float2bfloat16(wv[(o * CIN + i) * 9 + t]);
    }
}

// ---------------- x transpose: [b][c][n] fp32 -> [b][n][c] bf16 -------------------
__global__ void transpose_x_kernel(const float* __restrict__ x) {
    __shared__ float t[32][33];
    int b = blockIdx.z, n0 = blockIdx.x * 32, c0 = blockIdx.y * 32;
    int tid = threadIdx.x, nl = tid & 31, cg = tid >> 5;
#pragma unroll
    for (int i = 0; i < 4; i++) {
        int c = cg + i * 8;
        t[c][nl] = x[((size_t)b * CIN + c0 + c) * NPIX + n0 + nl];
    }
    __syncthreads();
    __nv_bfloat162 h0 = __floats2bfloat162_rn(t[cg * 4 + 0][nl], t[cg * 4 + 1][nl]);
    __nv_bfloat162 h1 = __floats2bfloat162_rn(t[cg * 4 + 2][nl], t[cg * 4 + 3][nl]);
    uint2 v;
    v.x = *(uint32_t*)&h0; v.y = *(uint32_t*)&h1;
    *(uint2*)(g_xT + ((size_t)b * NPIX + n0 + nl) * CIN + c0 + cg * 4) = v;
}

// ---------------- conv as implicit NT GEMM (bf16 mma.sync) ------------------------
// out[b][n][co] = bias[co] + sum_tap sum_ci wb[tap][co][ci] * xT[b][n+off_tap][ci]
// BM=128 pixels, BN=128 couts, BK=64, double-buffered cp.async; halo via src_size=0.
template <int COUT, int NTAPS>
__global__ __launch_bounds__(256) void conv_mma_kernel(const float* __restrict__ bias_v) {
    extern __shared__ unsigned char smem[];
    uint32_t sb = smem_u32(smem);
    const uint32_t AB0 = sb, BB0 = sb + 32768;

    int tid = threadIdx.x, lane = tid & 31, wid = tid >> 5;
    int wm = wid & 3, wn = wid >> 2;
    int b = blockIdx.z, m0 = blockIdx.y * 128, c0 = blockIdx.x * 128;

    const __nv_bfloat16* xTb = g_xT + (size_t)b * NPIX * CIN;
    const __nv_bfloat16* wb  = (NTAPS == 9) ? g_wvb : g_wkb;
    __nv_bfloat16* outp      = (NTAPS == 9) ? g_V : g_Kb;

    // per-thread load slots (4 A-chunks + 4 B-chunks per stage)
    int arow[4], ach[4], ay[4], ax[4];
#pragma unroll
    for (int i = 0; i < 4; i++) {
        int idx = tid + i * 256;
        arow[i] = idx >> 3;
        ach[i]  = idx & 7;
        int p = m0 + arow[i];
        ay[i] = p / IMGW;
        ax[i] = p - ay[i] * IMGW;
    }

    const int NS = NTAPS * 4;
    auto load_stage = [&](int s, int buf) {
        int tap = (NTAPS == 9) ? (s >> 2) : 0;
        int kc  = s & 3;
        int dy = (NTAPS == 9) ? (tap / 3 - 1) : 0;
        int dx = (NTAPS == 9) ? (tap % 3 - 1) : 0;
        int off = dy * IMGW + dx;
        uint32_t ab = AB0 + buf * 16384, bb = BB0 + buf * 16384;
#pragma unroll
        for (int i = 0; i < 4; i++) {
            bool valid = (NTAPS == 1) ||
                         (((unsigned)(ay[i] + dy) < (unsigned)IMGW) &&
                          ((unsigned)(ax[i] + dx) < (unsigned)IMGW));
            int srow = m0 + arow[i] + (valid ? off : 0);
            cpa16(ab + arow[i] * 128 + ((ach[i] ^ (arow[i] & 7)) << 4),
                  xTb + (size_t)srow * CIN + kc * 64 + ach[i] * 8, valid ? 16 : 0);
            cpa16(bb + arow[i] * 128 + ((ach[i] ^ (arow[i] & 7)) << 4),
                  wb + (size_t)(tap * COUT + c0 + arow[i]) * CIN + kc * 64 + ach[i] * 8, 16);
        }
        CP_COMMIT();
    };

    float acc[2][8][4] = {};
    load_stage(0, 0);
    for (int s = 0; s < NS; s++) {
        if (s + 1 < NS) { load_stage(s + 1, (s + 1) & 1); CP_WAIT(1); }
        else            { CP_WAIT(0); }
        __syncthreads();
        uint32_t ab = AB0 + (s & 1) * 16384, bb = BB0 + (s & 1) * 16384;
#pragma unroll
        for (int kk = 0; kk < 4; kk++) {
            uint32_t a[2][4];
#pragma unroll
            for (int mt = 0; mt < 2; mt++) {
                int row = wm * 32 + mt * 16 + (lane & 15);
                int ch  = kk * 2 + (lane >> 4);
                ldsm4(a[mt], ab + row * 128 + ((ch ^ (row & 7)) << 4));
            }
            uint32_t bq[4][4];
#pragma unroll
            for (int np = 0; np < 4; np++) {
                int row = wn * 64 + np * 16 + (lane & 7) + ((lane >> 4) << 3);
                int ch  = kk * 2 + ((lane >> 3) & 1);
                ldsm4(bq[np], bb + row * 128 + ((ch ^ (row & 7)) << 4));
            }
#pragma unroll
            for (int mt = 0; mt < 2; mt++)
#pragma unroll
                for (int np = 0; np < 4; np++) {
                    mma_bf16(acc[mt][2 * np],     a[mt], bq[np][0], bq[np][1]);
                    mma_bf16(acc[mt][2 * np + 1], a[mt], bq[np][2], bq[np][3]);
                }
        }
        __syncthreads();
    }
    // epilogue: + bias, write bf16 [b][n][cout]
#pragma unroll
    for (int mt = 0; mt < 2; mt++) {
        int r0 = m0 + wm * 32 + mt * 16 + (lane >> 2);
#pragma unroll
        for (int half = 0; half < 2; half++) {
            int rr = r0 + half * 8;
            __nv_bfloat16* op = outp + ((size_t)b * NPIX + rr) * COUT + c0;
#pragma unroll
            for (int nt = 0; nt < 8; nt++) {
                int col = wn * 64 + nt * 8 + (lane & 3) * 2;
                float b0 = (NTAPS == 9) ? bias_v[c0 + col]     : g_kbias[c0 + col];
                float b1 = (NTAPS == 9) ? bias_v[c0 + col + 1] : g_kbias[c0 + col + 1];
                __nv_bfloat162 h = __floats2bfloat162_rn(acc[mt][nt][half * 2] + b0,
                                                         acc[mt][nt][half * 2 + 1] + b1);
                *(uint32_t*)(op + col) = *(uint32_t*)&h;
            }
        }
    }
}

// ---------------- S = K @ K^T (bf16 mma.sync, K=128 single-shot) ------------------
__global__ __launch_bounds__(256) void attn_s_kernel() {
    extern __shared__ unsigned char smem[];
    uint32_t sb = smem_u32(smem);
    const uint32_t SA = sb, SB = sb + 32768;
    int tid = threadIdx.x, lane = tid & 31, wid = tid >> 5;
    int wm = wid & 3, wn = wid >> 2;
    int b = blockIdx.z, m0 = blockIdx.y * 128, n0 = blockIdx.x * 128;

    const __nv_bfloat16* KA = g_Kb + (size_t)(b * NPIX + m0) * CK;
    const __nv_bfloat16* KB = g_Kb + (size_t)(b * NPIX + n0) * CK;
#pragma unroll
    for (int i = 0; i < 8; i++) {
        int idx = tid + i * 256;
        int row = idx >> 4, ch = idx & 15;
        uint32_t off = row * 256 + ((ch ^ (row & 7)) << 4);
        cpa16(SA + off, KA + (size_t)row * CK + ch * 8, 16);
        cpa16(SB + off, KB + (size_t)row * CK + ch * 8, 16);
    }
    CP_COMMIT();
    CP_WAIT(0);
    __syncthreads();

    float acc[2][8][4] = {};
#pragma unroll
    for (int kk = 0; kk < 8; kk++) {
        uint32_t a[2][4];
#pragma unroll
        for (int mt = 0; mt < 2; mt++) {
            int row = wm * 32 + mt * 16 + (lane & 15);
            int ch  = kk * 2 + (lane >> 4);
            ldsm4(a[mt], SA + row * 256 + ((ch ^ (row & 7)) << 4));
        }
        uint32_t bq[4][4];
#pragma unroll
        for (int np = 0; np < 4; np++) {
            int row = wn * 64 + np * 16 + (lane & 7) + ((lane >> 4) << 3);
            int ch  = kk * 2 + ((lane >> 3) & 1);
            ldsm4(bq[np], SB + row * 256 + ((ch ^ (row & 7)) << 4));
        }
#pragma unroll
        for (int mt = 0; mt < 2; mt++)
#pragma unroll
            for (int np = 0; np < 4; np++) {
                mma_bf16(acc[mt][2 * np],     a[mt], bq[np][0], bq[np][1]);
                mma_bf16(acc[mt][2 * np + 1], a[mt], bq[np][2], bq[np][3]);
            }
    }
#pragma unroll
    for (int mt = 0; mt < 2; mt++) {
        int r0 = m0 + wm * 32 + mt * 16 + (lane >> 2);
#pragma unroll
        for (int half = 0; half < 2; half++) {
            int rr = r0 + half * 8;
            __nv_bfloat16* Sp = g_Sb + ((size_t)b * NPIX + rr) * NPIX + n0;
#pragma unroll
            for (int nt = 0; nt < 8; nt++) {
                int col = wn * 64 + nt * 8 + (lane & 3) * 2;
                __nv_bfloat162 h = __floats2bfloat162_rn(acc[mt][nt][half * 2],
                                                         acc[mt][nt][half * 2 + 1]);
                *(uint32_t*)(Sp + col) = *(uint32_t*)&h;
            }
        }
    }
}

// ---------------- row softmax on bf16 S (normalized P in place) -------------------
__global__ void softmax_kernel() {
    __shared__ __nv_bfloat16 buf[NPIX];
    __shared__ float red[256];
    int b = blockIdx.y, row = blockIdx.x, tid = threadIdx.x;
    __nv_bfloat16* Sp = g_Sb + ((size_t)b * NPIX + row) * NPIX;

    float mx = -3.4e38f;
    for (int g = tid; g < NPIX / 8; g += 256) {
        uint4 v = *(const uint4*)(Sp + g * 8);
        *(uint4*)(buf + g * 8) = v;
        const __nv_bfloat162* h = (const __nv_bfloat162*)&v;
#pragma unroll
        for (int t = 0; t < 4; t++) {
            float2 f = __bfloat1622float2(h[t]);
            mx = fmaxf(mx, fmaxf(f.x, f.y));
        }
    }
    red[tid] = mx;
    __syncthreads();
    for (int s = 128; s > 0; s >>= 1) {
        if (tid < s) red[tid] = fmaxf(red[tid], red[tid + s]);
        __syncthreads();
    }
    float m = red[0];
    __syncthreads();

    float sum = 0.f;
    for (int g = tid; g < NPIX / 8; g += 256) {
        uint4 v = *(const uint4*)(buf + g * 8);
        const __nv_bfloat162* h = (const __nv_bfloat162*)&v;
#pragma unroll
        for (int t = 0; t < 4; t++) {
            float2 f = __bfloat1622float2(h[t]);
            sum += __expf(f.x - m) + __expf(f.y - m);
        }
    }
    red[tid] = sum;
    __syncthreads();
    for (int s = 128; s > 0; s >>= 1) {
        if (tid < s) red[tid] += red[tid + s];
        __syncthreads();
    }
    float inv = 1.0f / red[0];

    for (int g = tid; g < NPIX / 8; g += 256) {
        uint4 v = *(const uint4*)(buf + g * 8);
        const __nv_bfloat162* h = (const __nv_bfloat162*)&v;
        uint4 o;
        uint32_t* op = (uint32_t*)&o;
#pragma unroll
        for (int t = 0; t < 4; t++) {
            float2 f = __bfloat1622float2(h[t]);
            __nv_bfloat162 e = __floats2bfloat162_rn(__expf(f.x - m) * inv,
                                                     __expf(f.y - m) * inv);
            op[t] = *(uint32_t*)&e;
        }
        *(uint4*)(Sp + g * 8) = o;
    }
}

// ---------------- ctx = P @ V (bf16 mma.sync, K=6400 pipelined) -------------------
// A = P[q][k] (non-trans ldmatrix); B = V[k=pixel][cout] (trans ldmatrix).
__global__ __launch_bounds__(256) void attn_ctx_kernel() {
    extern __shared__ unsigned char smem[];
    uint32_t sb = smem_u32(smem);
    const uint32_t AB0 = sb, BB0 = sb + 32768;
    int tid = threadIdx.x, lane = tid & 31, wid = tid >> 5;
    int wm = wid & 3, wn = wid >> 2;
    int b = blockIdx.z, m0 = blockIdx.y * 128, c0 = blockIdx.x * 128;

    const __nv_bfloat16* Pb = g_Sb + (size_t)b * NPIX * NPIX;
    const __nv_bfloat16* Vb = g_V + (size_t)b * NPIX * CV;

    auto load_stage = [&](int kt, int buf) {
        uint32_t ab = AB0 + buf * 16384, bb = BB0 + buf * 16384;
#pragma unroll
        for (int i = 0; i < 4; i++) {
            int idx = tid + i * 256;
            int row = idx >> 3, ch = idx & 7;
            cpa16(ab + row * 128 + ((ch ^ (row & 7)) << 4),
                  Pb + (size_t)(m0 + row) * NPIX + kt * 64 + ch * 8, 16);
            int br = idx >> 4, bc = idx & 15;
            cpa16(bb + br * 256 + ((bc ^ (br & 7)) << 4),
                  Vb + (size_t)(kt * 64 + br) * CV + c0 + bc * 8, 16);
        }
        CP_COMMIT();
    };

    float acc[2][8][4] = {};
    load_stage(0, 0);
    for (int kt = 0; kt < 100; kt++) {
        if (kt + 1 < 100) { load_stage(kt + 1, (kt + 1) & 1); CP_WAIT(1); }
        else              { CP_WAIT(0); }
        __syncthreads();
        uint32_t ab = AB0 + (kt & 1) * 16384, bb = BB0 + (kt & 1) * 16384;
#pragma unroll
        for (int kk = 0; kk < 4; kk++) {
            uint32_t a[2][4];
#pragma unroll
            for (int mt = 0; mt < 2; mt++) {
                int row = wm * 32 + mt * 16 + (lane & 15);
                int ch  = kk * 2 + (lane >> 4);
                ldsm4(a[mt], ab + row * 128 + ((ch ^ (row & 7)) << 4));
            }
            uint32_t bq[4][4];
#pragma unroll
            for (int np = 0; np < 4; np++) {
                int krow = kk * 16 + (lane & 7) + ((lane >> 3) & 1) * 8;
                int nch  = wn * 8 + np * 2 + (lane >> 4);
                ldsm4t(bq[np], bb + krow * 256 + ((nch ^ (krow & 7)) << 4));
            }
#pragma unroll
            for (int mt = 0; mt < 2; mt++)
#pragma unroll
                for (int np = 0; np < 4; np++) {
                    mma_bf16(acc[mt][2 * np],     a[mt], bq[np][0], bq[np][1]);
                    mma_bf16(acc[mt][2 * np + 1], a[mt], bq[np][2], bq[np][3]);
                }
        }
        __syncthreads();
    }
    // epilogue: fp32 ctx [b][n][c]
#pragma unroll
    for (int mt = 0; mt < 2; mt++) {
        int r0 = m0 + wm * 32 + mt * 16 + (lane >> 2);
#pragma unroll
        for (int half = 0; half < 2; half++) {
            int rr = r0 + half * 8;
            float* cp = g_ctx + ((size_t)b * NPIX + rr) * CV + c0;
#pragma unroll
            for (int nt = 0; nt < 8; nt++) {
                int col = wn * 64 + nt * 8 + (lane & 3) * 2;
                float2 v = make_float2(acc[mt][nt][half * 2], acc[mt][nt][half * 2 + 1]);
                *(float2*)(cp + col) = v;
            }
        }
    }
}

// ---------------- out[b][co][n] = ww @ ctx^T + bw + x (fp32 SIMT) -----------------
__global__ void gemm_out_kernel(const float* __restrict__ ww, const float* __restrict__ bw,
                                const float* __restrict__ x, float* __restrict__ out) {
    __shared__ float As[16][132];
    __shared__ float Bs[16][132];
    int b   = blockIdx.z;
    int co0 = blockIdx.y * 128;
    int n0  = blockIdx.x * 128;
    const float* ctxb = g_ctx + (size_t)b * NPIX * CV;

    int tid  = threadIdx.x;
    int f4   = tid & 3;
    int lrow = tid >> 2;
    int tx = tid & 15, ty = tid >> 4;

    float acc[8][8];
#pragma unroll
    for (int r = 0; r < 8; r++)
#pragma unroll
        for (int c = 0; c < 8; c++) acc[r][c] = 0.f;

    for (int k0 = 0; k0 < CV; k0 += 16) {
        __syncthreads();
#pragma unroll
        for (int l = 0; l < 2; l++) {
            int row = lrow + 64 * l;
            float4 va = *(const float4*)(ww + (size_t)(co0 + row) * CV + k0 + f4 * 4);
            As[f4 * 4 + 0][row] = va.x; As[f4 * 4 + 1][row] = va.y;
            As[f4 * 4 + 2][row] = va.z; As[f4 * 4 + 3][row] = va.w;
            float4 vb = *(const float4*)(ctxb + (size_t)(n0 + row) * CV + k0 + f4 * 4);
            Bs[f4 * 4 + 0][row] = vb.x; Bs[f4 * 4 + 1][row] = vb.y;
            Bs[f4 * 4 + 2][row] = vb.z; Bs[f4 * 4 + 3][row] = vb.w;
        }
        __syncthreads();
#pragma unroll
        for (int kk = 0; kk < 16; kk++) {
            float a[8], bv[8];
#pragma unroll
            for (int r = 0; r < 8; r++) a[r] = As[kk][ty * 8 + r];
#pragma unroll
            for (int c = 0; c < 8; c++) bv[c] = Bs[kk][tx * 8 + c];
#pragma unroll
            for (int r = 0; r < 8; r++)
#pragma unroll
                for (int c = 0; c < 8; c++) acc[r][c] += a[r] * bv[c];
        }
    }
#pragma unroll
    for (int r = 0; r < 8; r++) {
        int co = co0 + ty * 8 + r;
        float bwv = bw[co];
        size_t xbase = ((size_t)b * CIN + co) * NPIX + n0 + tx * 8;
        size_t obase = ((size_t)b * CV  + co) * NPIX + n0 + tx * 8;
        float4 x0 = *(const float4*)(x + xbase);
        float4 x1 = *(const float4*)(x + xbase + 4);
        float4 o0, o1;
        o0.x = acc[r][0] + bwv + x0.x; o0.y = acc[r][1] + bwv + x0.y;
        o0.z = acc[r][2] + bwv + x0.z; o0.w = acc[r][3] + bwv + x0.w;
        o1.x = acc[r][4] + bwv + x1.x; o1.y = acc[r][5] + bwv + x1.y;
        o1.z = acc[r][6] + bwv + x1.z; o1.w = acc[r][7] + bwv + x1.w;
        *(float4*)(out + obase)     = o0;
        *(float4*)(out + obase + 4) = o1;
    }
}

// ---------------- launch ----------------------------------------------------------
extern "C" void kernel_launch(void* const* d_in, const int* in_sizes, int n_in,
                              void* d_out, int out_size) {
    (void)in_sizes; (void)n_in; (void)out_size;
    const float* x     = (const float*)d_in[0];
    const float* wk    = (const float*)d_in[1];
    const float* bk    = (const float*)d_in[2];
    const float* gamma = (const float*)d_in[3];
    const float* beta  = (const float*)d_in[4];
    const float* rmean = (const float*)d_in[5];
    const float* rvar  = (const float*)d_in[6];
    const float* wv    = (const float*)d_in[7];
    const float* bv    = (const float*)d_in[8];
    const float* ww    = (const float*)d_in[9];
    const float* bw    = (const float*)d_in[10];
    float* out = (float*)d_out;

    const int MMA_SMEM = 65536;
    cudaFuncSetAttribute(conv_mma_kernel<CK, 1>, cudaFuncAttributeMaxDynamicSharedMemorySize, MMA_SMEM);
    cudaFuncSetAttribute(conv_mma_kernel<CV, 9>, cudaFuncAttributeMaxDynamicSharedMemorySize, MMA_SMEM);
    cudaFuncSetAttribute(attn_s_kernel, cudaFuncAttributeMaxDynamicSharedMemorySize, MMA_SMEM);
    cudaFuncSetAttribute(attn_ctx_kernel, cudaFuncAttributeMaxDynamicSharedMemorySize, MMA_SMEM);

    prep_kernel<<<256, 256>>>(wk, bk, gamma, beta, rmean, rvar, wv);
    transpose_x_kernel<<<dim3(NPIX / 32, CIN / 32, 2), 256>>>(x);
    conv_mma_kernel<CK, 1><<<dim3(1, NPIX / 128, 2), 256, MMA_SMEM>>>(bv);
    conv_mma_kernel<CV, 9><<<dim3(CV / 128, NPIX / 128, 2), 256, MMA_SMEM>>>(bv);
    attn_s_kernel<<<dim3(NPIX / 128, NPIX / 128, 2), 256, MMA_SMEM>>>();
    softmax_kernel<<<dim3(NPIX, 2), 256>>>();
    attn_ctx_kernel<<<dim3(CV / 128, NPIX / 128, 2), 256, MMA_SMEM>>>();
    gemm_out_kernel<<<dim3(NPIX / 128, CV / 128, 2), 256>>>(ww, bw, x, out);
}